// round 5
// baseline (speedup 1.0000x reference)
#include <cuda_runtime.h>
#include <cstddef>

// ---------------- problem constants ----------------
#define NW    8192          // words
#define LW    24            // chars per word
#define D     256           // model dim
#define NH    8             // heads
#define HD    32            // head dim
#define DFF   1024
#define NC    1024          // concepts
#define MAXW  16
#define M1    (NW*LW)       // 196608 tokens, block 1
#define M2    (NC*MAXW)     // 16384 tokens, block 2

// ---------------- scratch (device globals; no cudaMalloc allowed) ----------------
__device__ float g_x   [(size_t)M1*D];      // embeddings / word_ft
__device__ float g_qkv [(size_t)M1*3*D];    // fused qkv
__device__ float g_attn[(size_t)M1*D];      // attention out / name_ft
__device__ float g_t   [(size_t)M1*D];      // gemm temp (o-proj / ff2 out)
__device__ float g_h   [(size_t)M1*D];      // post-attn LN
__device__ float g_ff  [(size_t)M1*DFF];    // ff intermediate
__device__ float g_pad [(size_t)M2*D];      // padded [NC, MAXW, D]

// ---------------- embedding gather ----------------
__global__ void embed_k(const int* __restrict__ toks, const float* __restrict__ emb,
                        float* __restrict__ x, int total) {
    int i = blockIdx.x * blockDim.x + threadIdx.x;
    if (i < total) {
        int tok = toks[i >> 8];           // i / D
        x[i] = emb[tok * D + (i & 255)];  // i % D
    }
}

__global__ void zero_k(float* __restrict__ p, int n) {
    int i = blockIdx.x * blockDim.x + threadIdx.x;
    if (i < n) p[i] = 0.f;
}

// ---------------- fp32 SGEMM: C[M,N] = op(A[M,K] @ B[K,N]) ----------------
// 128x128 block tile, BK=8, 256 threads, 8x8 per-thread tile.
// Requires M%128==0, N%128==0, K%8==0 (true for all shapes here).
template<bool RELU>
__global__ void __launch_bounds__(256) sgemm_k(const float* __restrict__ A,
                                               const float* __restrict__ B,
                                               float* __restrict__ C,
                                               int M, int N, int K) {
    __shared__ float As[8][128];
    __shared__ float Bs[8][128];
    const int bm = blockIdx.y * 128;
    const int bn = blockIdx.x * 128;
    const int t  = threadIdx.x;

    const int arow = t >> 1, ac4 = (t & 1) * 4;   // A: 128 rows x 8 cols (2 float4/row)
    const int brow = t >> 5, bc4 = (t & 31) * 4;  // B: 8 rows x 128 cols
    const int rb = (t >> 4) * 8;                  // output row base within tile
    const int cb = (t & 15) * 8;                  // output col base within tile

    float acc[8][8];
    #pragma unroll
    for (int i = 0; i < 8; i++)
        #pragma unroll
        for (int j = 0; j < 8; j++) acc[i][j] = 0.f;

    for (int k0 = 0; k0 < K; k0 += 8) {
        float4 av = *(const float4*)(A + (size_t)(bm + arow) * K + k0 + ac4);
        As[ac4 + 0][arow] = av.x;
        As[ac4 + 1][arow] = av.y;
        As[ac4 + 2][arow] = av.z;
        As[ac4 + 3][arow] = av.w;
        *(float4*)&Bs[brow][bc4] =
            *(const float4*)(B + (size_t)(k0 + brow) * N + bn + bc4);
        __syncthreads();

        #pragma unroll
        for (int k = 0; k < 8; k++) {
            float ra[8], rbv[8];
            *(float4*)&ra[0]  = *(float4*)&As[k][rb];
            *(float4*)&ra[4]  = *(float4*)&As[k][rb + 4];
            *(float4*)&rbv[0] = *(float4*)&Bs[k][cb];
            *(float4*)&rbv[4] = *(float4*)&Bs[k][cb + 4];
            #pragma unroll
            for (int i = 0; i < 8; i++)
                #pragma unroll
                for (int j = 0; j < 8; j++) acc[i][j] += ra[i] * rbv[j];
        }
        __syncthreads();
    }

    #pragma unroll
    for (int i = 0; i < 8; i++) {
        float out[8];
        #pragma unroll
        for (int j = 0; j < 8; j++)
            out[j] = RELU ? fmaxf(acc[i][j], 0.f) : acc[i][j];
        float* cp = C + (size_t)(bm + rb + i) * N + bn + cb;
        *(float4*)cp       = *(float4*)&out[0];
        *(float4*)(cp + 4) = *(float4*)&out[4];
    }
}

// ---------------- attention: one block per word, one warp per head ----------------
// smem holds the word's full fused QKV [LT, 768]. Lane l < LT owns query row l.
template<int LT, bool MASKED>
__global__ void __launch_bounds__(256) attn_k(const float* __restrict__ qkv,
                                              const int* __restrict__ toks,
                                              float* __restrict__ out) {
    extern __shared__ float s[];   // LT * 768 floats
    __shared__ int smask[32];
    const int w = blockIdx.x, tid = threadIdx.x;

    const float4* base = (const float4*)(qkv + (size_t)w * LT * 768);
    float4* s4 = (float4*)s;
    for (int i = tid; i < LT * 192; i += 256) s4[i] = base[i];
    if (MASKED) {
        if (tid < LT) smask[tid] = (toks[(size_t)w * LT + tid] == 0);
    }
    __syncthreads();

    const int h = tid >> 5, lane = tid & 31;
    if (lane < LT) {
        float q[HD];
        const float* qp = s + lane * 768 + h * HD;
        #pragma unroll
        for (int d = 0; d < HD; d++) q[d] = qp[d];

        float p[LT];
        float mx = -1e30f;
        #pragma unroll
        for (int j = 0; j < LT; j++) {
            const float* kp = s + j * 768 + 256 + h * HD;
            float a = 0.f;
            #pragma unroll
            for (int d = 0; d < HD; d++) a += q[d] * kp[d];
            a *= 0.17677669529663687f;   // 1/sqrt(32)
            if (MASKED && smask[j]) a = -1e9f;
            p[j] = a;
            mx = fmaxf(mx, a);
        }
        float sum = 0.f;
        #pragma unroll
        for (int j = 0; j < LT; j++) { p[j] = expf(p[j] - mx); sum += p[j]; }
        const float inv = 1.f / sum;

        float* op = out + ((size_t)w * LT + lane) * D + h * HD;
        #pragma unroll
        for (int d = 0; d < HD; d++) {
            float a = 0.f;
            #pragma unroll
            for (int j = 0; j < LT; j++) a += p[j] * s[j * 768 + 512 + h * HD + d];
            op[d] = a * inv;
        }
    }
}

// ---------------- residual add + LayerNorm (no affine), one block per row ----------------
__global__ void __launch_bounds__(256) addln_k(const float* __restrict__ a,
                                               const float* __restrict__ b,
                                               float* __restrict__ o) {
    const int row = blockIdx.x, tid = threadIdx.x;
    const size_t idx = (size_t)row * D + tid;
    const float v = a[idx] + b[idx];

    __shared__ float red[8];
    float s = v;
    #pragma unroll
    for (int off = 16; off; off >>= 1) s += __shfl_xor_sync(0xffffffffu, s, off);
    if ((tid & 31) == 0) red[tid >> 5] = s;
    __syncthreads();
    float tot = 0.f;
    #pragma unroll
    for (int i = 0; i < 8; i++) tot += red[i];
    const float mean = tot * (1.f / 256.f);
    const float dv = v - mean;
    __syncthreads();

    s = dv * dv;
    #pragma unroll
    for (int off = 16; off; off >>= 1) s += __shfl_xor_sync(0xffffffffu, s, off);
    if ((tid & 31) == 0) red[tid >> 5] = s;
    __syncthreads();
    float tot2 = 0.f;
    #pragma unroll
    for (int i = 0; i < 8; i++) tot2 += red[i];
    const float var = tot2 * (1.f / 256.f);

    o[idx] = dv * rsqrtf(var + 1e-5f);
}

// ---------------- masked mean over chars + scatter into padded ----------------
__global__ void pool_k(const float* __restrict__ wft, const int* __restrict__ toks,
                       const int* __restrict__ cid, const int* __restrict__ wpos,
                       float* __restrict__ pad) {
    const int w = blockIdx.x, d = threadIdx.x;
    __shared__ int val[LW];
    if (d < LW) val[d] = (toks[(size_t)w * LW + d] != 0);
    __syncthreads();
    float ssum = 0.f; int cnt = 0;
    #pragma unroll
    for (int j = 0; j < LW; j++) {
        if (val[j]) { ssum += wft[((size_t)w * LW + j) * D + d]; cnt++; }
    }
    pad[((size_t)cid[w] * MAXW + wpos[w]) * D + d] = ssum / (float)cnt;
}

// ---------------- final: zero pad rows, per-dim nonzero counts, pooled mean ----------------
__global__ void final_k(const float* __restrict__ nf, const float* __restrict__ pad,
                        float* __restrict__ out) {
    const int c = blockIdx.x, d = threadIdx.x;
    __shared__ int nz[MAXW];
    if (d < MAXW) nz[d] = 0;
    __syncthreads();
    #pragma unroll
    for (int w = 0; w < MAXW; w++) {
        if (pad[((size_t)c * MAXW + w) * D + d] != 0.f) atomicOr(&nz[w], 1);
    }
    __syncthreads();
    float ssum = 0.f; int cnt = 0;
    #pragma unroll
    for (int w = 0; w < MAXW; w++) {
        if (nz[w]) {
            float v = nf[((size_t)c * MAXW + w) * D + d];
            ssum += v;
            cnt += (v != 0.f);
        }
    }
    out[(size_t)c * D + d] = ssum / (float)cnt;
}

// ---------------- driver ----------------
extern "C" void kernel_launch(void* const* d_in, const int* in_sizes, int n_in,
                              void* d_out, int out_size) {
    const int* toks = (const int*)d_in[0];
    const int* cid  = (const int*)d_in[1];
    const int* wpos = (const int*)d_in[2];

    // weights start at the unique 128*256-element we_emb (scalars n_concepts /
    // n_names may or may not be materialized as size-1 tensors before it)
    int wi = 3;
    while (wi < n_in && in_sizes[wi] != 128 * 256) wi++;
    const float* we_emb = (const float*)d_in[wi + 0];
    const float* we_qkv = (const float*)d_in[wi + 1];
    const float* we_o   = (const float*)d_in[wi + 2];
    const float* we_ff1 = (const float*)d_in[wi + 3];
    const float* we_ff2 = (const float*)d_in[wi + 4];
    const float* ne_qkv = (const float*)d_in[wi + 5];
    const float* ne_o   = (const float*)d_in[wi + 6];
    const float* ne_ff1 = (const float*)d_in[wi + 7];
    const float* ne_ff2 = (const float*)d_in[wi + 8];
    float* out = (float*)d_out;

    float *x, *qkv, *attn, *t, *h, *ff, *pad;
    cudaGetSymbolAddress((void**)&x,    g_x);
    cudaGetSymbolAddress((void**)&qkv,  g_qkv);
    cudaGetSymbolAddress((void**)&attn, g_attn);
    cudaGetSymbolAddress((void**)&t,    g_t);
    cudaGetSymbolAddress((void**)&h,    g_h);
    cudaGetSymbolAddress((void**)&ff,   g_ff);
    cudaGetSymbolAddress((void**)&pad,  g_pad);

    cudaFuncSetAttribute(attn_k<LW, true>,
                         cudaFuncAttributeMaxDynamicSharedMemorySize, LW * 768 * 4);
    cudaFuncSetAttribute(attn_k<MAXW, false>,
                         cudaFuncAttributeMaxDynamicSharedMemorySize, MAXW * 768 * 4);

    // ===== block 1 (char transformer over 196608 tokens) =====
    embed_k<<<(M1 * D + 255) / 256, 256>>>(toks, we_emb, x, M1 * D);

    sgemm_k<false><<<dim3(3 * D / 128, M1 / 128), 256>>>(x, we_qkv, qkv, M1, 3 * D, D);
    attn_k<LW, true><<<NW, 256, LW * 768 * 4>>>(qkv, toks, attn);
    sgemm_k<false><<<dim3(D / 128, M1 / 128), 256>>>(attn, we_o, t, M1, D, D);
    addln_k<<<M1, 256>>>(x, t, h);
    sgemm_k<true ><<<dim3(DFF / 128, M1 / 128), 256>>>(h, we_ff1, ff, M1, DFF, D);
    sgemm_k<false><<<dim3(D / 128, M1 / 128), 256>>>(ff, we_ff2, t, M1, D, DFF);
    addln_k<<<M1, 256>>>(h, t, x);   // word_ft -> x

    // ===== pool chars -> words, scatter into padded [NC, MAXW, D] =====
    zero_k<<<(M2 * D + 255) / 256, 256>>>(pad, M2 * D);
    pool_k<<<NW, 256>>>(x, toks, cid, wpos, pad);

    // ===== block 2 (name transformer over 16384 tokens, no mask) =====
    sgemm_k<false><<<dim3(3 * D / 128, M2 / 128), 256>>>(pad, ne_qkv, qkv, M2, 3 * D, D);
    attn_k<MAXW, false><<<NC, 256, MAXW * 768 * 4>>>(qkv, nullptr, attn);
    sgemm_k<false><<<dim3(D / 128, M2 / 128), 256>>>(attn, ne_o, t, M2, D, D);
    addln_k<<<M2, 256>>>(pad, t, h);
    sgemm_k<true ><<<dim3(DFF / 128, M2 / 128), 256>>>(h, ne_ff1, ff, M2, DFF, D);
    sgemm_k<false><<<dim3(D / 128, M2 / 128), 256>>>(ff, ne_ff2, t, M2, D, DFF);
    addln_k<<<M2, 256>>>(h, t, attn); // name_ft -> attn

    // ===== pad-row zeroing + per-dim nonzero-count mean -> output =====
    final_k<<<NC, 256>>>(attn, pad, out);
}